// round 6
// baseline (speedup 1.0000x reference)
#include <cuda_runtime.h>

#define B_  4
#define O_  32
#define C_  32
#define HW_ 32
#define P_  5
#define T_  (C_ * 9)      // 288 taps per output channel
#define EPSF 1e-6f
#define TS_ 35            // x-tile row stride (floats): bank = (3*row+col)%32

typedef unsigned long long u64;

__device__ __forceinline__ u64 pk(float lo, float hi) {
    u64 r; asm("mov.b64 %0, {%1, %2};" : "=l"(r) : "f"(lo), "f"(hi)); return r;
}
__device__ __forceinline__ void upk(float& lo, float& hi, u64 v) {
    asm("mov.b64 {%0, %1}, %2;" : "=f"(lo), "=f"(hi) : "l"(v));
}
// Packed fp32 fma (sm_103a FFMA2; no .sat variant exists)
__device__ __forceinline__ u64 fma2(u64 a, u64 b, u64 c) {
    u64 d; asm("fma.rn.f32x2 %0, %1, %2, %3;" : "=l"(d) : "l"(a), "l"(b), "l"(c));
    return d;
}
// sat(t) via scalar FFMA with IMMEDIATE multiplier 1.0 (rt_SMSP = 1 form).
// Bit-identical to fusing .sat into the producing fma: sat(rn(x*inv+nq)).
__device__ __forceinline__ float satf(float t) {
    float d;
    asm("fma.rn.sat.f32 %0, %1, 0f3F800000, 0f00000000;" : "=f"(d) : "f"(t));
    return d;
}
// u2 = x2*inv2 + nq2 (packed); sat per half (rt-1 imm-FFMA); acc2 += us2*dv2.
__device__ __forceinline__ void seg2(u64 x2, u64& acc, u64 inv2, u64 nq2, u64 dv2) {
    u64 u = fma2(x2, inv2, nq2);
    float lo, hi; upk(lo, hi, u);
    u64 s = pk(satf(lo), satf(hi));
    acc = fma2(s, dv2, acc);
}

// ---------------------------------------------------------------------------
// Fused kernel. Grid: 1024 = (b, o, 4-row strip of 8). Block: 256 = 8 warps.
// (1024 blocks -> per-SM block-count skew ~1.2% vs 33% at 512.)
// Phase 0: sort this o's 288 (pos,val)[5] tables (Bose-Nelson 9 CE) ->
//   clamped-ramp coefficients stored DUPLICATED for packed math (per tap 6
//   u64 pairs). f(x) = v0 + sum_k dv_k * sat((x-p_k)*inv_k) == reference.
// Phase 1: warp w handles channels 4w..4w+3 over the whole 4-row strip;
//   4 px/thread as two packed pairs. x in double-buffered 6x34 tiles
//   (stride 35 -> conflict-free). Tables via uniform LDS.128 broadcast.
// Phase 2: 8-way float4 smem reduction + bias, STG.128.
// ---------------------------------------------------------------------------
__global__ __launch_bounds__(256, 4) void pc_fused(const float* __restrict__ x,
                                                   const float* __restrict__ pos,
                                                   const float* __restrict__ val,
                                                   float* __restrict__ out) {
    const int blk = blockIdx.x;
    const int strip = blk & 7;             // 0..7 : 4-row strip
    const int o = (blk >> 3) & 31;
    const int b = blk >> 8;
    const int y0 = strip * 4;

    __shared__ ulonglong2 s_tab[T_ * 6];    // 27648 B duplicated coeffs
    __shared__ float      s_v0[T_];         // 1152 B
    __shared__ float      s_x[16][6 * TS_]; // 2 tiles/warp, 13440 B
    __shared__ float4     s_red[8][32];     // 4096 B
    __shared__ float      s_bias;

    const int tid = threadIdx.x;

    // ---- Phase 0: build duplicated coefficient tables for this o ----
    const float* pbase = pos + o * (T_ * P_);
    const float* vbase = val + o * (T_ * P_);
#pragma unroll
    for (int rep = 0; rep < 2; rep++) {
        int ot = tid + rep * 256;
        if (ot < T_) {
            float p[P_], v[P_];
#pragma unroll
            for (int k = 0; k < P_; k++) { p[k] = pbase[ot * P_ + k]; v[k] = vbase[ot * P_ + k]; }
#define CE(a, bb) do { if (p[a] > p[bb]) { float t0 = p[a]; p[a] = p[bb]; p[bb] = t0; \
                                           float t1 = v[a]; v[a] = v[bb]; v[bb] = t1; } } while (0)
            CE(0,1); CE(3,4); CE(2,4); CE(2,3); CE(1,4); CE(0,3); CE(0,2); CE(1,3); CE(1,2);
#undef CE
            float* tf = (float*)(s_tab + ot * 6);   // 24 floats per tap
#pragma unroll
            for (int k = 0; k < 4; k++) {
                float den = p[k + 1] - p[k] + EPSF;
                float inv = 1.0f / den;
                float nq  = -p[k] * inv;
                float dv  = v[k + 1] - v[k];
                tf[4 * k + 0] = inv; tf[4 * k + 1] = inv;
                tf[4 * k + 2] = nq;  tf[4 * k + 3] = nq;
                tf[16 + 2 * k + 0] = dv; tf[16 + 2 * k + 1] = dv;
            }
            s_v0[ot] = v[0];
        }
    }
    __syncthreads();

    if (tid < 32) {
        float s = 0.0f;
#pragma unroll
        for (int k = 0; k < 9; k++) s += s_v0[tid + k * 32];
#pragma unroll
        for (int off = 16; off > 0; off >>= 1) s += __shfl_down_sync(0xffffffffu, s, off);
        if (tid == 0) s_bias = s;
    }
    __syncthreads();

    // ---- Phase 1 ----
    const int warp = tid >> 5;
    const int lane = tid & 31;
    const int rl   = lane >> 3;            // 0..3: row within strip
    const int xg   = (lane & 7) * 4;       // 0,4,...,28
    const int rowbase = y0 - 1;            // tile row 0 = global row y0-1

    int  rowoff[6];
    bool okA[6], okB[6];
#pragma unroll
    for (int rr = 0; rr < 6; rr++) {
        int gy = rowbase + rr;
        bool rowok = (gy >= 0) && (gy < HW_);
        rowoff[rr] = gy * HW_;
        okA[rr] = rowok && (lane >= 1);
        okB[rr] = rowok && (lane == 0);
    }

    u64 acc01 = pk(0.0f, 0.0f);
    u64 acc23 = acc01;

    const float* xb = x + b * (C_ * HW_ * HW_);
    const int cBase = warp * 4;            // 4 channels per warp
    const float* xc = xb + cBase * (HW_ * HW_);
    float* tA = s_x[warp * 2];
    float* tB = s_x[warp * 2 + 1];

#define FILL(T_PTR, XC) do {                                               \
    const float* xp_ = (XC);                                               \
    _Pragma("unroll")                                                      \
    for (int rr = 0; rr < 6; rr++) {                                       \
        float v_ = okA[rr] ? xp_[rowoff[rr] + lane - 1] : 0.0f;            \
        (T_PTR)[rr * TS_ + lane] = v_;                                     \
        if (lane < 2) {                                                    \
            float v2_ = okB[rr] ? xp_[rowoff[rr] + 31] : 0.0f;             \
            (T_PTR)[rr * TS_ + 32 + lane] = v2_;                           \
        }                                                                  \
    } } while (0)

    FILL(tA, xc);                          // prefetch first channel

    for (int cc = 0; cc < 4; cc++) {
        float* cur = (cc & 1) ? tB : tA;
        float* nxt = (cc & 1) ? tA : tB;
        __syncwarp();

        float vreg[3][6];
#pragma unroll
        for (int ii = 0; ii < 3; ii++)
#pragma unroll
            for (int jj = 0; jj < 6; jj++)
                vreg[ii][jj] = cur[(rl + ii) * TS_ + xg + jj];

        if (cc < 3) FILL(nxt, xc + (HW_ * HW_));
        xc += HW_ * HW_;

        const ulonglong2* tp = s_tab + (cBase + cc) * 9 * 6;
#pragma unroll
        for (int i = 0; i < 3; i++) {
#pragma unroll
            for (int j = 0; j < 3; j++) {
                const ulonglong2* t6 = tp + (i * 3 + j) * 6;
                ulonglong2 s0 = t6[0];     // (inv0,inv0),(nq0,nq0) -- broadcast
                ulonglong2 s1 = t6[1];
                ulonglong2 s2 = t6[2];
                ulonglong2 s3 = t6[3];
                ulonglong2 d01 = t6[4];    // (dv0,dv0),(dv1,dv1)
                ulonglong2 d23 = t6[5];    // (dv2,dv2),(dv3,dv3)
                u64 x01 = pk(vreg[i][j + 0], vreg[i][j + 1]);
                u64 x23 = pk(vreg[i][j + 2], vreg[i][j + 3]);
                seg2(x01, acc01, s0.x, s0.y, d01.x);
                seg2(x23, acc23, s0.x, s0.y, d01.x);
                seg2(x01, acc01, s1.x, s1.y, d01.y);
                seg2(x23, acc23, s1.x, s1.y, d01.y);
                seg2(x01, acc01, s2.x, s2.y, d23.x);
                seg2(x23, acc23, s2.x, s2.y, d23.x);
                seg2(x01, acc01, s3.x, s3.y, d23.y);
                seg2(x23, acc23, s3.x, s3.y, d23.y);
            }
        }
    }
#undef FILL

    // ---- Phase 2: reduce across the 8 warps ----
    float a0, a1, a2, a3;
    upk(a0, a1, acc01);
    upk(a2, a3, acc23);
    const int g = rl * 8 + (lane & 7);     // 0..31 pixel group within strip
    s_red[warp][g] = make_float4(a0, a1, a2, a3);
    __syncthreads();

    if (tid < 32) {
        float bias = s_bias;
        float4 r0 = s_red[0][tid];
        float4 r1 = s_red[1][tid];
        float4 r2 = s_red[2][tid];
        float4 r3 = s_red[3][tid];
        float4 r4 = s_red[4][tid];
        float4 r5 = s_red[5][tid];
        float4 r6 = s_red[6][tid];
        float4 r7 = s_red[7][tid];
        float4 res;
        res.x = bias + ((r0.x + r1.x) + (r2.x + r3.x)) + ((r4.x + r5.x) + (r6.x + r7.x));
        res.y = bias + ((r0.y + r1.y) + (r2.y + r3.y)) + ((r4.y + r5.y) + (r6.y + r7.y));
        res.z = bias + ((r0.z + r1.z) + (r2.z + r3.z)) + ((r4.z + r5.z) + (r6.z + r7.z));
        res.w = bias + ((r0.w + r1.w) + (r2.w + r3.w)) + ((r4.w + r5.w) + (r6.w + r7.w));
        int row = tid >> 3;
        int col0 = (tid & 7) * 4;
        int oidx = ((b * O_ + o) * HW_ + y0 + row) * HW_ + col0;
        *reinterpret_cast<float4*>(out + oidx) = res;
    }
}

extern "C" void kernel_launch(void* const* d_in, const int* in_sizes, int n_in,
                              void* d_out, int out_size) {
    const float* x   = (const float*)d_in[0];
    const float* pos = (const float*)d_in[1];
    const float* val = (const float*)d_in[2];
    float* out = (float*)d_out;

    pc_fused<<<B_ * O_ * 8, 256>>>(x, pos, val, out);
}

// round 7
// speedup vs baseline: 1.1383x; 1.1383x over previous
#include <cuda_runtime.h>

#define B_  4
#define O_  32
#define C_  32
#define HW_ 32
#define P_  5
#define T_  (C_ * 9)      // 288 taps per output channel
#define EPSF 1e-6f
#define TS_ 36            // x-tile row stride (floats), 16B-aligned rows

// ---------------------------------------------------------------------------
// Max-affine formulation: per sorted tap table,
//   f(x) = const + sum_{k=0..4} g_k * max(x, p_k)
// == the reference's eps-regularized piecewise-linear interp + boundary clamps
// (slopes telescope; const folded into a global bias).
// Per pixel-tap: 5 FMNMX (alu pipe) + 5 FFMA (fma pipe) — both rt-2 pipes
// loaded equally, halving the per-pipe cycle count vs the all-FFMA form.
//
// Grid: 1024 = (b, o, 4-row strip). Block: 256 = 8 warps; warp w handles
// channels 4w..4w+3 over the strip, 4 px/thread. x per-warp double-buffered
// 6x36 tile (LDS.128+LDS.64 reads). Tables via uniform LDS.128 broadcast.
// 8-way float4 smem reduction + bias, STG.128.
// ---------------------------------------------------------------------------
__global__ __launch_bounds__(256, 4) void pc_fused(const float* __restrict__ x,
                                                   const float* __restrict__ pos,
                                                   const float* __restrict__ val,
                                                   float* __restrict__ out) {
    const int blk = blockIdx.x;
    const int strip = blk & 7;             // 0..7 : 4-row strip
    const int o = (blk >> 3) & 31;
    const int b = blk >> 8;
    const int y0 = strip * 4;

    __shared__ float4 s_tab[T_ * 3];        // per tap: {p0..p3},{g0..g3},{p4,g4,-,-}
    __shared__ float  s_cst[T_];
    __shared__ float  s_x[16][6 * TS_];     // 2 tiles/warp
    __shared__ float4 s_red[8][32];
    __shared__ float  s_bias;

    const int tid = threadIdx.x;

    // ---- Phase 0: sort + build max-affine coefficients for this o ----
    const float* pbase = pos + o * (T_ * P_);
    const float* vbase = val + o * (T_ * P_);
#pragma unroll
    for (int rep = 0; rep < 2; rep++) {
        int ot = tid + rep * 256;
        if (ot < T_) {
            float p[P_], v[P_];
#pragma unroll
            for (int k = 0; k < P_; k++) { p[k] = pbase[ot * P_ + k]; v[k] = vbase[ot * P_ + k]; }
#define CE(a, bb) do { if (p[a] > p[bb]) { float t0 = p[a]; p[a] = p[bb]; p[bb] = t0; \
                                           float t1 = v[a]; v[a] = v[bb]; v[bb] = t1; } } while (0)
            CE(0,1); CE(3,4); CE(2,4); CE(2,3); CE(1,4); CE(0,3); CE(0,2); CE(1,3); CE(1,2);
#undef CE
            float s[4];
#pragma unroll
            for (int k = 0; k < 4; k++)
                s[k] = (v[k + 1] - v[k]) / (p[k + 1] - p[k] + EPSF);
            float g0 = s[0];
            float g1 = s[1] - s[0];
            float g2 = s[2] - s[1];
            float g3 = s[3] - s[2];
            float g4 = -s[3];
            float cst = v[0] - (g0 * p[0] + g1 * p[1] + g2 * p[2] + g3 * p[3] + g4 * p[4]);
            s_tab[ot * 3 + 0] = make_float4(p[0], p[1], p[2], p[3]);
            s_tab[ot * 3 + 1] = make_float4(g0, g1, g2, g3);
            s_tab[ot * 3 + 2] = make_float4(p[4], g4, 0.0f, 0.0f);
            s_cst[ot] = cst;
        }
    }
    __syncthreads();

    if (tid < 32) {        // bias = sum_t const_t
        float s = 0.0f;
#pragma unroll
        for (int k = 0; k < 9; k++) s += s_cst[tid + k * 32];
#pragma unroll
        for (int off = 16; off > 0; off >>= 1) s += __shfl_down_sync(0xffffffffu, s, off);
        if (tid == 0) s_bias = s;
    }
    __syncthreads();

    // ---- Phase 1 ----
    const int warp = tid >> 5;
    const int lane = tid & 31;
    const int rl   = lane >> 3;            // 0..3: row within strip
    const int xg   = (lane & 7) * 4;       // 0,4,...,28
    const int rowbase = y0 - 1;

    int  rowoff[6];
    bool okA[6], okB[6];
#pragma unroll
    for (int rr = 0; rr < 6; rr++) {
        int gy = rowbase + rr;
        bool rowok = (gy >= 0) && (gy < HW_);
        rowoff[rr] = gy * HW_;
        okA[rr] = rowok && (lane >= 1);
        okB[rr] = rowok && (lane == 0);
    }

    float acc0 = 0.0f, acc1 = 0.0f, acc2 = 0.0f, acc3 = 0.0f;

    const float* xb = x + b * (C_ * HW_ * HW_);
    const int cBase = warp * 4;
    const float* xc = xb + cBase * (HW_ * HW_);
    float* tA = s_x[warp * 2];
    float* tB = s_x[warp * 2 + 1];

#define FILL(T_PTR, XC) do {                                               \
    const float* xp_ = (XC);                                               \
    _Pragma("unroll")                                                      \
    for (int rr = 0; rr < 6; rr++) {                                       \
        float v_ = okA[rr] ? xp_[rowoff[rr] + lane - 1] : 0.0f;            \
        (T_PTR)[rr * TS_ + lane] = v_;                                     \
        if (lane < 2) {                                                    \
            float v2_ = okB[rr] ? xp_[rowoff[rr] + 31] : 0.0f;             \
            (T_PTR)[rr * TS_ + 32 + lane] = v2_;                           \
        }                                                                  \
    } } while (0)

// One max-affine term for all 4 pixels: FMNMX (alu) + FFMA (fma) each.
#define TERM(PK, GK) do {                                                  \
        acc0 = fmaf((GK), fmaxf(xv0, (PK)), acc0);                         \
        acc1 = fmaf((GK), fmaxf(xv1, (PK)), acc1);                         \
        acc2 = fmaf((GK), fmaxf(xv2, (PK)), acc2);                         \
        acc3 = fmaf((GK), fmaxf(xv3, (PK)), acc3);                         \
    } while (0)

    FILL(tA, xc);                          // prefetch first channel

    for (int cc = 0; cc < 4; cc++) {
        float* cur = (cc & 1) ? tB : tA;
        float* nxt = (cc & 1) ? tA : tB;
        __syncwarp();

        // 3 rows x 6 cols neighborhood via LDS.128 + LDS.64 (rows 16B-aligned)
        float vreg[3][6];
#pragma unroll
        for (int ii = 0; ii < 3; ii++) {
            const float* rp = cur + (rl + ii) * TS_ + xg;
            float4 a = *reinterpret_cast<const float4*>(rp);
            float2 bb = *reinterpret_cast<const float2*>(rp + 4);
            vreg[ii][0] = a.x; vreg[ii][1] = a.y; vreg[ii][2] = a.z;
            vreg[ii][3] = a.w; vreg[ii][4] = bb.x; vreg[ii][5] = bb.y;
        }

        if (cc < 3) FILL(nxt, xc + (HW_ * HW_));
        xc += HW_ * HW_;

        const float4* tp = s_tab + (cBase + cc) * 27;
#pragma unroll
        for (int i = 0; i < 3; i++) {
#pragma unroll
            for (int j = 0; j < 3; j++) {
                float4 P = tp[(i * 3 + j) * 3 + 0];   // uniform -> broadcast
                float4 G = tp[(i * 3 + j) * 3 + 1];
                float4 E = tp[(i * 3 + j) * 3 + 2];   // (p4, g4, -, -)
                float xv0 = vreg[i][j + 0];
                float xv1 = vreg[i][j + 1];
                float xv2 = vreg[i][j + 2];
                float xv3 = vreg[i][j + 3];
                TERM(P.x, G.x);
                TERM(P.y, G.y);
                TERM(P.z, G.z);
                TERM(P.w, G.w);
                TERM(E.x, E.y);
            }
        }
    }
#undef TERM
#undef FILL

    // ---- Phase 2: reduce across the 8 warps ----
    const int g = rl * 8 + (lane & 7);
    s_red[warp][g] = make_float4(acc0, acc1, acc2, acc3);
    __syncthreads();

    if (tid < 32) {
        float bias = s_bias;
        float4 r0 = s_red[0][tid];
        float4 r1 = s_red[1][tid];
        float4 r2 = s_red[2][tid];
        float4 r3 = s_red[3][tid];
        float4 r4 = s_red[4][tid];
        float4 r5 = s_red[5][tid];
        float4 r6 = s_red[6][tid];
        float4 r7 = s_red[7][tid];
        float4 res;
        res.x = bias + ((r0.x + r1.x) + (r2.x + r3.x)) + ((r4.x + r5.x) + (r6.x + r7.x));
        res.y = bias + ((r0.y + r1.y) + (r2.y + r3.y)) + ((r4.y + r5.y) + (r6.y + r7.y));
        res.z = bias + ((r0.z + r1.z) + (r2.z + r3.z)) + ((r4.z + r5.z) + (r6.z + r7.z));
        res.w = bias + ((r0.w + r1.w) + (r2.w + r3.w)) + ((r4.w + r5.w) + (r6.w + r7.w));
        int row = tid >> 3;
        int col0 = (tid & 7) * 4;
        int oidx = ((b * O_ + o) * HW_ + y0 + row) * HW_ + col0;
        *reinterpret_cast<float4*>(out + oidx) = res;
    }
}

extern "C" void kernel_launch(void* const* d_in, const int* in_sizes, int n_in,
                              void* d_out, int out_size) {
    const float* x   = (const float*)d_in[0];
    const float* pos = (const float*)d_in[1];
    const float* val = (const float*)d_in[2];
    float* out = (float*)d_out;

    pc_fused<<<B_ * O_ * 8, 256>>>(x, pos, val, out);
}